// round 13
// baseline (speedup 1.0000x reference)
#include <cuda_runtime.h>
#include <cuda_fp16.h>
#include <math.h>
#include <stdint.h>

#define N_NODES 50000
#define E_EDGES 800000
#define DIM     128
#define NHEADS  8
#define DHEAD   16
#define NLAYERS 2

// ---------------- scratch (static device globals; no runtime allocation) ----------------
__device__ float  g_h[N_NODES * DIM];
__device__ float  g_q[N_NODES * DIM];
__device__ __half g_kh[N_NODES * DIM];
__device__ __half g_vh[N_NODES * DIM];
__device__ float  g_attn[N_NODES * DIM];
__device__ float  g_hx[N_NODES * DIM];
__device__ float  g_f1[N_NODES * 2 * DIM];
__device__ int    g_deg[N_NODES + 1];
__device__ int    g_cur[N_NODES];
__device__ int    g_off[N_NODES + 1];
__device__ int    g_csr[E_EDGES];     // stores SRC NODE id per CSR slot (not edge id)
__device__ int    g_bt[64];
__device__ int    g_bo[64];

// ---------------- small utility kernels ----------------
__global__ void k_zero2(int* a, int na, int* b, int nb) {
    int i = blockIdx.x * blockDim.x + threadIdx.x;
    if (i < na) a[i] = 0;
    if (i < nb) b[i] = 0;
}

__global__ void k_hist(const int* __restrict__ dst, int* __restrict__ deg, int e) {
    int i = blockIdx.x * blockDim.x + threadIdx.x;
    if (i < e) atomicAdd(&deg[dst[i]], 1);
}

// ---------- multi-block exclusive scan ----------
__global__ void k_s1(const int* __restrict__ deg, int* __restrict__ bt) {
    int b = blockIdx.x, t = threadIdx.x, lane = t & 31, w = t >> 5;
    int base = b * 1024 + t * 4;
    int s = 0;
    #pragma unroll
    for (int j = 0; j < 4; ++j) { int i = base + j; if (i < N_NODES) s += deg[i]; }
    #pragma unroll
    for (int o = 16; o > 0; o >>= 1) s += __shfl_xor_sync(0xffffffffu, s, o);
    __shared__ int ws[8];
    if (lane == 0) ws[w] = s;
    __syncthreads();
    if (t == 0) {
        int tt = 0;
        #pragma unroll
        for (int i = 0; i < 8; ++i) tt += ws[i];
        bt[b] = tt;
    }
}

__global__ void k_s2(const int* __restrict__ bt, int* __restrict__ bo,
                     int* __restrict__ off, int nb) {
    __shared__ int sm[64];
    int t = threadIdx.x;
    int v = (t < nb) ? bt[t] : 0;
    sm[t] = v;
    __syncthreads();
    for (int o = 1; o < 64; o <<= 1) {
        int u = (t >= o) ? sm[t - o] : 0;
        __syncthreads();
        sm[t] += u;
        __syncthreads();
    }
    if (t < nb) bo[t] = sm[t] - v;
    if (t == 0) off[N_NODES] = E_EDGES;
}

__global__ void k_s3(const int* __restrict__ deg, const int* __restrict__ bo,
                     int* __restrict__ off) {
    int b = blockIdx.x, t = threadIdx.x, lane = t & 31, w = t >> 5;
    int base = b * 1024 + t * 4;
    int d[4];
    #pragma unroll
    for (int j = 0; j < 4; ++j) { int i = base + j; d[j] = (i < N_NODES) ? deg[i] : 0; }
    int tsum = d[0] + d[1] + d[2] + d[3];
    int inc = tsum;
    #pragma unroll
    for (int o = 1; o < 32; o <<= 1) {
        int u = __shfl_up_sync(0xffffffffu, inc, o);
        if (lane >= o) inc += u;
    }
    int exc = inc - tsum;
    __shared__ int ws[8];
    if (lane == 31) ws[w] = inc;
    __syncthreads();
    int woff = 0;
    for (int i = 0; i < w; ++i) woff += ws[i];
    int run = bo[b] + woff + exc;
    #pragma unroll
    for (int j = 0; j < 4; ++j) {
        int i = base + j;
        if (i < N_NODES) off[i] = run;
        run += d[j];
    }
}

// store the SRC NODE directly into the CSR slot (kills one indirection in k_attn)
__global__ void k_fill(const int* __restrict__ dst, const int* __restrict__ src,
                       int* __restrict__ cur, const int* __restrict__ off,
                       int* __restrict__ csr, int e) {
    int i = blockIdx.x * blockDim.x + threadIdx.x;
    if (i < e) {
        int d = dst[i];
        int p = atomicAdd(&cur[d], 1);
        csr[off[d] + p] = src[i];
    }
}

// ---------------- TF32 tensor-core GEMM, BK=16, 3-stage cp.async, 1 barrier/iter ----------------
// C[M,NC] = A[M,K] @ B[K,NC] (+bias)(+resid)(relu?)(+fused LayerNorm when lnw!=null)
// When Ch != null, output is packed fp16 (half2 stores) instead of fp32 C.
// BM=128 BN=128 BK=16, 256 threads, warp grid 2(m) x 4(n), warp tile 64x32.
// __launch_bounds__(256,3): 3 blocks/SM (84-reg cap) -> single-wave 391-block launches.
// Dynamic smem: 3*(128*20 + 16*136) floats = 56832 bytes (x3 blocks = 170KB < 227KB).

#define A_STG (128 * 20)
#define B_STG (16 * 136)
#define NSTG  3
#define SMEM_BYTES ((NSTG * (A_STG + B_STG)) * 4)

__device__ __forceinline__ uint32_t f2tf32(float f) {
    uint32_t r;
    asm("cvt.rna.tf32.f32 %0, %1;" : "=r"(r) : "f"(f));
    return r;
}

__device__ __forceinline__ void mma_tf32(float c[4], uint32_t a0, uint32_t a1,
                                         uint32_t a2, uint32_t a3,
                                         uint32_t b0, uint32_t b1) {
    asm volatile(
        "mma.sync.aligned.m16n8k8.row.col.f32.tf32.tf32.f32 "
        "{%0,%1,%2,%3}, {%4,%5,%6,%7}, {%8,%9}, {%0,%1,%2,%3};\n"
        : "+f"(c[0]), "+f"(c[1]), "+f"(c[2]), "+f"(c[3])
        : "r"(a0), "r"(a1), "r"(a2), "r"(a3), "r"(b0), "r"(b1));
}

__device__ __forceinline__ void cp16(uint32_t saddr, const void* gaddr, bool pred) {
    int sz = pred ? 16 : 0;
    asm volatile("cp.async.cg.shared.global [%0], [%1], 16, %2;\n"
                 :: "r"(saddr), "l"(gaddr), "r"(sz));
}
__device__ __forceinline__ void cp_commit() {
    asm volatile("cp.async.commit_group;\n");
}
__device__ __forceinline__ void cp_wait1() {
    asm volatile("cp.async.wait_group 1;\n");
}
__device__ __forceinline__ void cp_wait0() {
    asm volatile("cp.async.wait_group 0;\n");
}

__device__ __forceinline__ void gemm_body(
    const float* __restrict__ A, const float* __restrict__ B,
    const float* __restrict__ bias, const float* __restrict__ resid,
    float* __restrict__ C, __half* __restrict__ Ch,
    int M, int K, int NC, int relu,
    const float* __restrict__ lnw, const float* __restrict__ lnb)
{
    extern __shared__ float smem[];
    float* Asm = smem;                       // [NSTG][128][20]
    float* Bsm = smem + NSTG * A_STG;        // [NSTG][16][136]

    const int tid = threadIdx.x;
    const int lane = tid & 31;
    const int wid = tid >> 5;
    const int wm = wid >> 2;       // 0..1
    const int wn = wid & 3;        // 0..3
    const int g  = lane >> 2;      // 0..7
    const int tg = lane & 3;       // 0..3

    const int bm = blockIdx.x * 128;
    const int bn = blockIdx.y * 128;

    const int ar0 = tid >> 2;           // 0..63
    const int ar1 = ar0 + 64;
    const int ac4 = tid & 3;
    const int br0 = tid >> 5;           // 0..7
    const int br1 = br0 + 8;
    const int bc4 = tid & 31;

    const bool a0v = (bm + ar0) < M;
    const bool a1v = (bm + ar1) < M;

    const uint32_t sA = (uint32_t)__cvta_generic_to_shared(Asm);
    const uint32_t sB = (uint32_t)__cvta_generic_to_shared(Bsm);
    const uint32_t sa0 = sA + (uint32_t)(ar0 * 20 + ac4 * 4) * 4;
    const uint32_t sa1 = sA + (uint32_t)(ar1 * 20 + ac4 * 4) * 4;
    const uint32_t sb0 = sB + (uint32_t)(br0 * 136 + bc4 * 4) * 4;
    const uint32_t sb1 = sB + (uint32_t)(br1 * 136 + bc4 * 4) * 4;
    const float* ga0 = A + (size_t)(bm + ar0) * K + ac4 * 4;
    const float* ga1 = A + (size_t)(bm + ar1) * K + ac4 * 4;
    const float* gb0 = B + (size_t)br0 * NC + bn + bc4 * 4;
    const float* gb1 = B + (size_t)br1 * NC + bn + bc4 * 4;

    float acc[4][4][4];
    #pragma unroll
    for (int i = 0; i < 4; ++i)
        #pragma unroll
        for (int j = 0; j < 4; ++j)
            #pragma unroll
            for (int r = 0; r < 4; ++r) acc[i][j][r] = 0.f;

    const int iters = K >> 4;

    // prologue: stages 0..NSTG-2 — ONE commit group per stage (A+B together)
    #pragma unroll
    for (int st = 0; st < NSTG - 1; ++st) {
        const int k0 = st * 16;
        cp16(sa0 + (uint32_t)(st * A_STG) * 4, ga0 + k0, a0v);
        cp16(sa1 + (uint32_t)(st * A_STG) * 4, ga1 + k0, a1v);
        cp16(sb0 + (uint32_t)(st * B_STG) * 4, gb0 + (size_t)k0 * NC, true);
        cp16(sb1 + (uint32_t)(st * B_STG) * 4, gb1 + (size_t)k0 * NC, true);
        cp_commit();
    }

    for (int kt = 0; kt < iters; ++kt) {
        const int st = kt % NSTG;
        if (kt < iters - 1) cp_wait1(); else cp_wait0();
        __syncthreads();   // single barrier per iter

        if (kt + NSTG - 1 < iters) {
            const int ns = (kt + NSTG - 1) % NSTG;
            const int k0 = (kt + NSTG - 1) * 16;
            cp16(sa0 + (uint32_t)(ns * A_STG) * 4, ga0 + k0, a0v);
            cp16(sa1 + (uint32_t)(ns * A_STG) * 4, ga1 + k0, a1v);
            cp16(sb0 + (uint32_t)(ns * B_STG) * 4, gb0 + (size_t)k0 * NC, true);
            cp16(sb1 + (uint32_t)(ns * B_STG) * 4, gb1 + (size_t)k0 * NC, true);
            cp_commit();
        }

        const float* Ast = Asm + st * A_STG;
        const float* Bst = Bsm + st * B_STG;
        #pragma unroll
        for (int s = 0; s < 2; ++s) {
            uint32_t af[4][4], bf[4][2];
            const int col = s * 8 + tg;
            #pragma unroll
            for (int mt = 0; mt < 4; ++mt) {
                const int rm = wm * 64 + mt * 16 + g;
                af[mt][0] = f2tf32(Ast[rm * 20 + col]);
                af[mt][1] = f2tf32(Ast[(rm + 8) * 20 + col]);
                af[mt][2] = f2tf32(Ast[rm * 20 + col + 4]);
                af[mt][3] = f2tf32(Ast[(rm + 8) * 20 + col + 4]);
            }
            #pragma unroll
            for (int nt = 0; nt < 4; ++nt) {
                const int cn = wn * 32 + nt * 8 + g;
                bf[nt][0] = f2tf32(Bst[(s * 8 + tg) * 136 + cn]);
                bf[nt][1] = f2tf32(Bst[(s * 8 + 4 + tg) * 136 + cn]);
            }
            #pragma unroll
            for (int mt = 0; mt < 4; ++mt)
                #pragma unroll
                for (int nt = 0; nt < 4; ++nt)
                    mma_tf32(acc[mt][nt], af[mt][0], af[mt][1], af[mt][2], af[mt][3],
                             bf[nt][0], bf[nt][1]);
        }
    }
    __syncthreads();

    if (lnw == nullptr) {
        // plain epilogue: bias / resid / relu; fp32 or packed fp16 output
        #pragma unroll
        for (int mt = 0; mt < 4; ++mt) {
            const int r0 = bm + wm * 64 + mt * 16 + g;
            const int r1 = r0 + 8;
            #pragma unroll
            for (int nt = 0; nt < 4; ++nt) {
                const int gc = bn + wn * 32 + nt * 8 + tg * 2;
                float2 o0 = make_float2(acc[mt][nt][0], acc[mt][nt][1]);
                float2 o1 = make_float2(acc[mt][nt][2], acc[mt][nt][3]);
                if (bias) {
                    float2 bb = *(const float2*)&bias[gc];
                    o0.x += bb.x; o0.y += bb.y;
                    o1.x += bb.x; o1.y += bb.y;
                }
                if (r0 < M) {
                    if (resid) {
                        float2 rr = *(const float2*)&resid[(size_t)r0 * NC + gc];
                        o0.x += rr.x; o0.y += rr.y;
                    }
                    if (relu) { o0.x = fmaxf(o0.x, 0.f); o0.y = fmaxf(o0.y, 0.f); }
                    if (Ch) *(half2*)&Ch[(size_t)r0 * NC + gc] = __floats2half2_rn(o0.x, o0.y);
                    else    *(float2*)&C[(size_t)r0 * NC + gc] = o0;
                }
                if (r1 < M) {
                    if (resid) {
                        float2 rr = *(const float2*)&resid[(size_t)r1 * NC + gc];
                        o1.x += rr.x; o1.y += rr.y;
                    }
                    if (relu) { o1.x = fmaxf(o1.x, 0.f); o1.y = fmaxf(o1.y, 0.f); }
                    if (Ch) *(half2*)&Ch[(size_t)r1 * NC + gc] = __floats2half2_rn(o1.x, o1.y);
                    else    *(float2*)&C[(size_t)r1 * NC + gc] = o1;
                }
            }
        }
        return;
    }

    // ---- fused LayerNorm epilogue (NC==128, gridDim.y==1) ----
    #pragma unroll
    for (int mt = 0; mt < 4; ++mt) {
        const int r0 = bm + wm * 64 + mt * 16 + g;
        const int r1 = r0 + 8;
        #pragma unroll
        for (int nt = 0; nt < 4; ++nt) {
            const int gc = wn * 32 + nt * 8 + tg * 2;
            float2 bb = *(const float2*)&bias[gc];
            acc[mt][nt][0] += bb.x; acc[mt][nt][1] += bb.y;
            acc[mt][nt][2] += bb.x; acc[mt][nt][3] += bb.y;
            if (r0 < M) {
                float2 rr = *(const float2*)&resid[(size_t)r0 * NC + gc];
                acc[mt][nt][0] += rr.x; acc[mt][nt][1] += rr.y;
            }
            if (r1 < M) {
                float2 rr = *(const float2*)&resid[(size_t)r1 * NC + gc];
                acc[mt][nt][2] += rr.x; acc[mt][nt][3] += rr.y;
            }
        }
    }
    float* lnsum = smem;            // [128][4]
    float* lnsq  = smem + 512;      // [128][4]
    #pragma unroll
    for (int mt = 0; mt < 4; ++mt) {
        float s0 = 0.f, q0 = 0.f, s1 = 0.f, q1 = 0.f;
        #pragma unroll
        for (int nt = 0; nt < 4; ++nt) {
            float a = acc[mt][nt][0], b = acc[mt][nt][1];
            float c = acc[mt][nt][2], d = acc[mt][nt][3];
            s0 += a + b; q0 += a * a + b * b;
            s1 += c + d; q1 += c * c + d * d;
        }
        #pragma unroll
        for (int o = 1; o < 4; o <<= 1) {
            s0 += __shfl_xor_sync(0xffffffffu, s0, o);
            q0 += __shfl_xor_sync(0xffffffffu, q0, o);
            s1 += __shfl_xor_sync(0xffffffffu, s1, o);
            q1 += __shfl_xor_sync(0xffffffffu, q1, o);
        }
        if (tg == 0) {
            const int lr0 = wm * 64 + mt * 16 + g;
            lnsum[lr0 * 4 + wn] = s0;  lnsq[lr0 * 4 + wn] = q0;
            lnsum[(lr0 + 8) * 4 + wn] = s1;  lnsq[(lr0 + 8) * 4 + wn] = q1;
        }
    }
    __syncthreads();
    #pragma unroll
    for (int mt = 0; mt < 4; ++mt) {
        const int lr0 = wm * 64 + mt * 16 + g;
        const int lr1 = lr0 + 8;
        float4 sv0 = *(const float4*)&lnsum[lr0 * 4];
        float4 qv0 = *(const float4*)&lnsq[lr0 * 4];
        float4 sv1 = *(const float4*)&lnsum[lr1 * 4];
        float4 qv1 = *(const float4*)&lnsq[lr1 * 4];
        float m0 = (sv0.x + sv0.y + sv0.z + sv0.w) * (1.f / 128.f);
        float m1 = (sv1.x + sv1.y + sv1.z + sv1.w) * (1.f / 128.f);
        float v0 = (qv0.x + qv0.y + qv0.z + qv0.w) * (1.f / 128.f) - m0 * m0;
        float v1 = (qv1.x + qv1.y + qv1.z + qv1.w) * (1.f / 128.f) - m1 * m1;
        float rs0 = rsqrtf(v0 + 1e-5f);
        float rs1 = rsqrtf(v1 + 1e-5f);
        const int r0 = bm + lr0;
        const int r1 = bm + lr1;
        #pragma unroll
        for (int nt = 0; nt < 4; ++nt) {
            const int gc = wn * 32 + nt * 8 + tg * 2;
            float2 wv = *(const float2*)&lnw[gc];
            float2 bv = *(const float2*)&lnb[gc];
            if (r0 < M) {
                float2 o;
                o.x = (acc[mt][nt][0] - m0) * rs0 * wv.x + bv.x;
                o.y = (acc[mt][nt][1] - m0) * rs0 * wv.y + bv.y;
                *(float2*)&C[(size_t)r0 * NC + gc] = o;
            }
            if (r1 < M) {
                float2 o;
                o.x = (acc[mt][nt][2] - m1) * rs1 * wv.x + bv.x;
                o.y = (acc[mt][nt][3] - m1) * rs1 * wv.y + bv.y;
                *(float2*)&C[(size_t)r1 * NC + gc] = o;
            }
        }
    }
}

__global__ __launch_bounds__(256, 3) void gemm_tf32(
    const float* __restrict__ A, const float* __restrict__ B,
    const float* __restrict__ bias, const float* __restrict__ resid,
    float* __restrict__ C, int M, int K, int NC, int relu)
{
    gemm_body(A, B, bias, resid, C, nullptr, M, K, NC, relu, nullptr, nullptr);
}

__global__ __launch_bounds__(256, 3) void gemm_tf32_ln(
    const float* __restrict__ A, const float* __restrict__ B,
    const float* __restrict__ bias, const float* __restrict__ resid,
    float* __restrict__ C, int M, int K, int NC,
    const float* __restrict__ lnw, const float* __restrict__ lnb)
{
    gemm_body(A, B, bias, resid, C, nullptr, M, K, NC, 0, lnw, lnb);
}

// fused Q/K/V: blockIdx.z selects weight/bias/output; K and V outputs packed fp16
__global__ __launch_bounds__(256, 3) void gemm_qkv(
    const float* __restrict__ A,
    const float* __restrict__ Bq, const float* __restrict__ Bk, const float* __restrict__ Bv,
    const float* __restrict__ bq, const float* __restrict__ bk, const float* __restrict__ bv,
    float* __restrict__ Cq, __half* __restrict__ Ckh, __half* __restrict__ Cvh,
    int M, int K, int NC)
{
    const int zi = blockIdx.z;
    const float* B  = (zi == 0) ? Bq : (zi == 1) ? Bk : Bv;
    const float* bb = (zi == 0) ? bq : (zi == 1) ? bk : bv;
    float*  C  = (zi == 0) ? Cq : nullptr;
    __half* Ch = (zi == 0) ? nullptr : (zi == 1) ? Ckh : Cvh;
    gemm_body(A, B, bb, nullptr, C, Ch, M, K, NC, 0, nullptr, nullptr);
}

// ---------------- edge attention gather: one warp per dst node, fp16 k/v ----------------
// csr[j] holds the src node id directly (single indirection).
__global__ __launch_bounds__(256) void k_attn(
    const float* __restrict__ q, const __half* __restrict__ kh, const __half* __restrict__ vh,
    const int* __restrict__ off, const int* __restrict__ csr,
    float* __restrict__ attn)
{
    int w = (blockIdx.x * blockDim.x + threadIdx.x) >> 5;
    int lane = threadIdx.x & 31;
    if (w >= N_NODES) return;
    float4 qv = *(const float4*)&q[(size_t)w * DIM + lane * 4];
    float4 acc = make_float4(0.f, 0.f, 0.f, 0.f);
    float z = 0.f;
    int j0 = off[w], j1 = off[w + 1];
    for (int j = j0; j < j1; ++j) {
        int sn = csr[j];
        const size_t base = (size_t)sn * DIM + lane * 4;
        uint2 kr = *(const uint2*)(kh + base);
        uint2 vr = *(const uint2*)(vh + base);
        float2 ka = __half22float2(*(half2*)&kr.x);
        float2 kb = __half22float2(*(half2*)&kr.y);
        float2 va = __half22float2(*(half2*)&vr.x);
        float2 vb = __half22float2(*(half2*)&vr.y);
        float d = ka.x * qv.x + ka.y * qv.y + kb.x * qv.z + kb.y * qv.w;
        d += __shfl_xor_sync(0xffffffffu, d, 1);
        d += __shfl_xor_sync(0xffffffffu, d, 2);
        float sc = __expf(fminf(fmaxf(d * 0.25f, -5.f), 5.f));
        acc.x += va.x * sc; acc.y += va.y * sc; acc.z += vb.x * sc; acc.w += vb.y * sc;
        z += sc;
    }
    float inv = 1.f / (z + 1e-6f);
    float4 o = make_float4(acc.x * inv, acc.y * inv, acc.z * inv, acc.w * inv);
    *(float4*)&attn[(size_t)w * DIM + lane * 4] = o;
}

// ---------------- host ----------------
extern "C" void kernel_launch(void* const* d_in, const int* in_sizes, int n_in,
                              void* d_out, int out_size)
{
    (void)in_sizes; (void)n_in; (void)out_size;
    const float* h_in  = (const float*)d_in[0];
    const int*   src   = (const int*)d_in[1];
    const int*   dst   = (const int*)d_in[2];
    const float* W_emb = (const float*)d_in[3];
    const float* Wq    = (const float*)d_in[4];
    const float* bq    = (const float*)d_in[5];
    const float* Wk    = (const float*)d_in[6];
    const float* bk    = (const float*)d_in[7];
    const float* Wv    = (const float*)d_in[8];
    const float* bv    = (const float*)d_in[9];
    const float* Wo    = (const float*)d_in[10];
    const float* bo    = (const float*)d_in[11];
    const float* ln1w  = (const float*)d_in[12];
    const float* ln1b  = (const float*)d_in[13];
    const float* Wf1   = (const float*)d_in[14];
    const float* bf1   = (const float*)d_in[15];
    const float* Wf2   = (const float*)d_in[16];
    const float* bf2   = (const float*)d_in[17];
    const float* ln2w  = (const float*)d_in[18];
    const float* ln2b  = (const float*)d_in[19];
    float* out = (float*)d_out;

    float *h, *q, *attn, *hx, *f1;
    __half *kh, *vh;
    int *deg, *cur, *off, *csr, *bt, *bo_;
    cudaGetSymbolAddress((void**)&h,    g_h);
    cudaGetSymbolAddress((void**)&q,    g_q);
    cudaGetSymbolAddress((void**)&kh,   g_kh);
    cudaGetSymbolAddress((void**)&vh,   g_vh);
    cudaGetSymbolAddress((void**)&attn, g_attn);
    cudaGetSymbolAddress((void**)&hx,   g_hx);
    cudaGetSymbolAddress((void**)&f1,   g_f1);
    cudaGetSymbolAddress((void**)&deg,  g_deg);
    cudaGetSymbolAddress((void**)&cur,  g_cur);
    cudaGetSymbolAddress((void**)&off,  g_off);
    cudaGetSymbolAddress((void**)&csr,  g_csr);
    cudaGetSymbolAddress((void**)&bt,   g_bt);
    cudaGetSymbolAddress((void**)&bo_,  g_bo);

    // opt-in to >48KB dynamic smem (idempotent; host-side attribute, capture-safe)
    static bool attr_done = false;
    if (!attr_done) {
        cudaFuncSetAttribute(gemm_tf32,    cudaFuncAttributeMaxDynamicSharedMemorySize, SMEM_BYTES);
        cudaFuncSetAttribute(gemm_tf32_ln, cudaFuncAttributeMaxDynamicSharedMemorySize, SMEM_BYTES);
        cudaFuncSetAttribute(gemm_qkv,     cudaFuncAttributeMaxDynamicSharedMemorySize, SMEM_BYTES);
        attr_done = true;
    }

    const int MB = (N_NODES + 127) / 128;                 // 391
    const int WARP_BLOCKS = (N_NODES * 32 + 255) / 256;   // 6250
    const int SCAN_BLOCKS = (N_NODES + 1023) / 1024;      // 49
    const dim3 blk(256);

    // Launch order arranged so ncu (-s 5) lands on a GEMM: slot3=emb, slot5=qkv.
    k_zero2<<<(N_NODES + 256) / 256, blk>>>(deg, N_NODES + 1, cur, N_NODES);      // 0
    k_hist<<<(E_EDGES + 255) / 256, blk>>>(dst, deg, E_EDGES);                    // 1
    k_s1<<<SCAN_BLOCKS, blk>>>(deg, bt);                                          // 2
    gemm_tf32<<<dim3(MB, 1), blk, SMEM_BYTES>>>(h_in, W_emb, nullptr, nullptr,    // 3
                                                h, N_NODES, DIM, DIM, 0);
    k_s2<<<1, 64>>>(bt, bo_, off, SCAN_BLOCKS);                                   // 4

    // layer 0 QKV (depends on emb only)                                          // 5
    gemm_qkv<<<dim3(MB, 1, 3), blk, SMEM_BYTES>>>(h, Wq, Wk, Wv, bq, bk, bv,
                                                  q, kh, vh, N_NODES, DIM, DIM);

    k_s3<<<SCAN_BLOCKS, blk>>>(deg, bo_, off);                                    // 6
    k_fill<<<(E_EDGES + 255) / 256, blk>>>(dst, src, cur, off, csr, E_EDGES);     // 7

    for (int l = 0; l < NLAYERS; ++l) {
        const float* wq = Wq + (size_t)l * DIM * DIM;
        const float* wk = Wk + (size_t)l * DIM * DIM;
        const float* wv = Wv + (size_t)l * DIM * DIM;
        const float* wo = Wo + (size_t)l * DIM * DIM;
        const float* wf1 = Wf1 + (size_t)l * DIM * 2 * DIM;
        const float* wf2 = Wf2 + (size_t)l * 2 * DIM * DIM;

        if (l > 0) {
            gemm_qkv<<<dim3(MB, 1, 3), blk, SMEM_BYTES>>>(h, wq, wk, wv,
                                                          bq + l * DIM, bk + l * DIM, bv + l * DIM,
                                                          q, kh, vh, N_NODES, DIM, DIM);
        }

        k_attn<<<WARP_BLOCKS, blk>>>(q, kh, vh, off, csr, attn);

        // hx = LN1(h + attn @ Wo + bo)   (LN fused into epilogue)
        gemm_tf32_ln<<<dim3(MB, 1), blk, SMEM_BYTES>>>(attn, wo, bo + l * DIM, h, hx,
                                                       N_NODES, DIM, DIM,
                                                       ln1w + l * DIM, ln1b + l * DIM);

        // f1 = relu(hx @ Wf1 + bf1)   [N, 256]
        gemm_tf32<<<dim3(MB, 2), blk, SMEM_BYTES>>>(hx, wf1, bf1 + l * 2 * DIM, nullptr, f1,
                                                    N_NODES, DIM, 2 * DIM, 1);

        // h_next = LN2(hx + f1 @ Wf2 + bf2)   (LN fused)
        float* lnout = (l == NLAYERS - 1) ? out : h;
        gemm_tf32_ln<<<dim3(MB, 1), blk, SMEM_BYTES>>>(f1, wf2, bf2 + l * DIM, hx, lnout,
                                                       N_NODES, 2 * DIM, DIM,
                                                       ln2w + l * DIM, ln2b + l * DIM);
    }
}

// round 14
// speedup vs baseline: 1.4778x; 1.4778x over previous
#include <cuda_runtime.h>
#include <cuda_fp16.h>
#include <math.h>
#include <stdint.h>

#define N_NODES 50000
#define E_EDGES 800000
#define DIM     128
#define NHEADS  8
#define DHEAD   16
#define NLAYERS 2

// ---------------- scratch (static device globals; no runtime allocation) ----------------
__device__ float  g_h[N_NODES * DIM];
__device__ float  g_q[N_NODES * DIM];
__device__ __half g_kh[N_NODES * DIM];
__device__ __half g_vh[N_NODES * DIM];
__device__ float  g_attn[N_NODES * DIM];
__device__ float  g_hx[N_NODES * DIM];
__device__ float  g_f1[N_NODES * 2 * DIM];
__device__ int    g_deg[N_NODES + 1];
__device__ int    g_cur[N_NODES];
__device__ int    g_off[N_NODES + 1];
__device__ int    g_csr[E_EDGES];     // stores SRC NODE id per CSR slot (not edge id)
__device__ int    g_bt[64];
__device__ int    g_bo[64];

// ---------------- small utility kernels ----------------
__global__ void k_zero2(int* a, int na, int* b, int nb) {
    int i = blockIdx.x * blockDim.x + threadIdx.x;
    if (i < na) a[i] = 0;
    if (i < nb) b[i] = 0;
}

__global__ void k_hist(const int* __restrict__ dst, int* __restrict__ deg, int e) {
    int i = blockIdx.x * blockDim.x + threadIdx.x;
    if (i < e) atomicAdd(&deg[dst[i]], 1);
}

// ---------- multi-block exclusive scan ----------
__global__ void k_s1(const int* __restrict__ deg, int* __restrict__ bt) {
    int b = blockIdx.x, t = threadIdx.x, lane = t & 31, w = t >> 5;
    int base = b * 1024 + t * 4;
    int s = 0;
    #pragma unroll
    for (int j = 0; j < 4; ++j) { int i = base + j; if (i < N_NODES) s += deg[i]; }
    #pragma unroll
    for (int o = 16; o > 0; o >>= 1) s += __shfl_xor_sync(0xffffffffu, s, o);
    __shared__ int ws[8];
    if (lane == 0) ws[w] = s;
    __syncthreads();
    if (t == 0) {
        int tt = 0;
        #pragma unroll
        for (int i = 0; i < 8; ++i) tt += ws[i];
        bt[b] = tt;
    }
}

__global__ void k_s2(const int* __restrict__ bt, int* __restrict__ bo,
                     int* __restrict__ off, int nb) {
    __shared__ int sm[64];
    int t = threadIdx.x;
    int v = (t < nb) ? bt[t] : 0;
    sm[t] = v;
    __syncthreads();
    for (int o = 1; o < 64; o <<= 1) {
        int u = (t >= o) ? sm[t - o] : 0;
        __syncthreads();
        sm[t] += u;
        __syncthreads();
    }
    if (t < nb) bo[t] = sm[t] - v;
    if (t == 0) off[N_NODES] = E_EDGES;
}

__global__ void k_s3(const int* __restrict__ deg, const int* __restrict__ bo,
                     int* __restrict__ off) {
    int b = blockIdx.x, t = threadIdx.x, lane = t & 31, w = t >> 5;
    int base = b * 1024 + t * 4;
    int d[4];
    #pragma unroll
    for (int j = 0; j < 4; ++j) { int i = base + j; d[j] = (i < N_NODES) ? deg[i] : 0; }
    int tsum = d[0] + d[1] + d[2] + d[3];
    int inc = tsum;
    #pragma unroll
    for (int o = 1; o < 32; o <<= 1) {
        int u = __shfl_up_sync(0xffffffffu, inc, o);
        if (lane >= o) inc += u;
    }
    int exc = inc - tsum;
    __shared__ int ws[8];
    if (lane == 31) ws[w] = inc;
    __syncthreads();
    int woff = 0;
    for (int i = 0; i < w; ++i) woff += ws[i];
    int run = bo[b] + woff + exc;
    #pragma unroll
    for (int j = 0; j < 4; ++j) {
        int i = base + j;
        if (i < N_NODES) off[i] = run;
        run += d[j];
    }
}

// store the SRC NODE directly into the CSR slot (kills one indirection in k_attn)
__global__ void k_fill(const int* __restrict__ dst, const int* __restrict__ src,
                       int* __restrict__ cur, const int* __restrict__ off,
                       int* __restrict__ csr, int e) {
    int i = blockIdx.x * blockDim.x + threadIdx.x;
    if (i < e) {
        int d = dst[i];
        int p = atomicAdd(&cur[d], 1);
        csr[off[d] + p] = src[i];
    }
}

// ---------------- TF32 tensor-core GEMM, BK=16, 4-stage cp.async, 1 barrier/iter ----------------
// C[M,NC] = A[M,K] @ B[K,NC] (+bias)(+resid)(relu?)(+fused LayerNorm when lnw!=null)
// When Ch != null, output is packed fp16 (half2 stores) instead of fp32 C.
// BM=128 BN=128 BK=16, 256 threads, warp grid 2(m) x 4(n), warp tile 64x32.
// EXACT R12 configuration (proven 21.2us/unit, 128 regs, 2 blocks/SM, no spills).

#define A_STG (128 * 20)
#define B_STG (16 * 136)
#define NSTG  4
#define SMEM_BYTES ((NSTG * (A_STG + B_STG)) * 4)

__device__ __forceinline__ uint32_t f2tf32(float f) {
    uint32_t r;
    asm("cvt.rna.tf32.f32 %0, %1;" : "=r"(r) : "f"(f));
    return r;
}

__device__ __forceinline__ void mma_tf32(float c[4], uint32_t a0, uint32_t a1,
                                         uint32_t a2, uint32_t a3,
                                         uint32_t b0, uint32_t b1) {
    asm volatile(
        "mma.sync.aligned.m16n8k8.row.col.f32.tf32.tf32.f32 "
        "{%0,%1,%2,%3}, {%4,%5,%6,%7}, {%8,%9}, {%0,%1,%2,%3};\n"
        : "+f"(c[0]), "+f"(c[1]), "+f"(c[2]), "+f"(c[3])
        : "r"(a0), "r"(a1), "r"(a2), "r"(a3), "r"(b0), "r"(b1));
}

__device__ __forceinline__ void cp16(uint32_t saddr, const void* gaddr, bool pred) {
    int sz = pred ? 16 : 0;
    asm volatile("cp.async.cg.shared.global [%0], [%1], 16, %2;\n"
                 :: "r"(saddr), "l"(gaddr), "r"(sz));
}
__device__ __forceinline__ void cp_commit() {
    asm volatile("cp.async.commit_group;\n");
}
__device__ __forceinline__ void cp_wait2() {
    asm volatile("cp.async.wait_group 2;\n");
}
__device__ __forceinline__ void cp_wait1() {
    asm volatile("cp.async.wait_group 1;\n");
}
__device__ __forceinline__ void cp_wait0() {
    asm volatile("cp.async.wait_group 0;\n");
}

__device__ __forceinline__ void gemm_body(
    const float* __restrict__ A, const float* __restrict__ B,
    const float* __restrict__ bias, const float* __restrict__ resid,
    float* __restrict__ C, __half* __restrict__ Ch,
    int M, int K, int NC, int relu,
    const float* __restrict__ lnw, const float* __restrict__ lnb)
{
    extern __shared__ float smem[];
    float* Asm = smem;                       // [NSTG][128][20]
    float* Bsm = smem + NSTG * A_STG;        // [NSTG][16][136]

    const int tid = threadIdx.x;
    const int lane = tid & 31;
    const int wid = tid >> 5;
    const int wm = wid >> 2;       // 0..1
    const int wn = wid & 3;        // 0..3
    const int g  = lane >> 2;      // 0..7
    const int tg = lane & 3;       // 0..3

    const int bm = blockIdx.x * 128;
    const int bn = blockIdx.y * 128;

    const int ar0 = tid >> 2;           // 0..63
    const int ar1 = ar0 + 64;
    const int ac4 = tid & 3;
    const int br0 = tid >> 5;           // 0..7
    const int br1 = br0 + 8;
    const int bc4 = tid & 31;

    const bool a0v = (bm + ar0) < M;
    const bool a1v = (bm + ar1) < M;

    const uint32_t sA = (uint32_t)__cvta_generic_to_shared(Asm);
    const uint32_t sB = (uint32_t)__cvta_generic_to_shared(Bsm);
    const uint32_t sa0 = sA + (uint32_t)(ar0 * 20 + ac4 * 4) * 4;
    const uint32_t sa1 = sA + (uint32_t)(ar1 * 20 + ac4 * 4) * 4;
    const uint32_t sb0 = sB + (uint32_t)(br0 * 136 + bc4 * 4) * 4;
    const uint32_t sb1 = sB + (uint32_t)(br1 * 136 + bc4 * 4) * 4;
    const float* ga0 = A + (size_t)(bm + ar0) * K + ac4 * 4;
    const float* ga1 = A + (size_t)(bm + ar1) * K + ac4 * 4;
    const float* gb0 = B + (size_t)br0 * NC + bn + bc4 * 4;
    const float* gb1 = B + (size_t)br1 * NC + bn + bc4 * 4;

    float acc[4][4][4];
    #pragma unroll
    for (int i = 0; i < 4; ++i)
        #pragma unroll
        for (int j = 0; j < 4; ++j)
            #pragma unroll
            for (int r = 0; r < 4; ++r) acc[i][j][r] = 0.f;

    const int iters = K >> 4;

    // prologue: stages 0..NSTG-2 — ONE commit group per stage (A+B together)
    #pragma unroll
    for (int st = 0; st < NSTG - 1; ++st) {
        const int k0 = st * 16;
        cp16(sa0 + (uint32_t)(st * A_STG) * 4, ga0 + k0, a0v);
        cp16(sa1 + (uint32_t)(st * A_STG) * 4, ga1 + k0, a1v);
        cp16(sb0 + (uint32_t)(st * B_STG) * 4, gb0 + (size_t)k0 * NC, true);
        cp16(sb1 + (uint32_t)(st * B_STG) * 4, gb1 + (size_t)k0 * NC, true);
        cp_commit();
    }

    for (int kt = 0; kt < iters; ++kt) {
        const int st = kt % NSTG;
        if (kt <= iters - 3)      cp_wait2();
        else if (kt == iters - 2) cp_wait1();
        else                      cp_wait0();
        __syncthreads();

        if (kt + NSTG - 1 < iters) {
            const int ns = (kt + NSTG - 1) % NSTG;
            const int k0 = (kt + NSTG - 1) * 16;
            cp16(sa0 + (uint32_t)(ns * A_STG) * 4, ga0 + k0, a0v);
            cp16(sa1 + (uint32_t)(ns * A_STG) * 4, ga1 + k0, a1v);
            cp16(sb0 + (uint32_t)(ns * B_STG) * 4, gb0 + (size_t)k0 * NC, true);
            cp16(sb1 + (uint32_t)(ns * B_STG) * 4, gb1 + (size_t)k0 * NC, true);
            cp_commit();
        }

        const float* Ast = Asm + st * A_STG;
        const float* Bst = Bsm + st * B_STG;
        #pragma unroll
        for (int s = 0; s < 2; ++s) {
            uint32_t af[4][4], bf[4][2];
            const int col = s * 8 + tg;
            #pragma unroll
            for (int mt = 0; mt < 4; ++mt) {
                const int rm = wm * 64 + mt * 16 + g;
                af[mt][0] = f2tf32(Ast[rm * 20 + col]);
                af[mt][1] = f2tf32(Ast[(rm + 8) * 20 + col]);
                af[mt][2] = f2tf32(Ast[rm * 20 + col + 4]);
                af[mt][3] = f2tf32(Ast[(rm + 8) * 20 + col + 4]);
            }
            #pragma unroll
            for (int nt = 0; nt < 4; ++nt) {
                const int cn = wn * 32 + nt * 8 + g;
                bf[nt][0] = f2tf32(Bst[(s * 8 + tg) * 136 + cn]);
                bf[nt][1] = f2tf32(Bst[(s * 8 + 4 + tg) * 136 + cn]);
            }
            #pragma unroll
            for (int mt = 0; mt < 4; ++mt)
                #pragma unroll
                for (int nt = 0; nt < 4; ++nt)
                    mma_tf32(acc[mt][nt], af[mt][0], af[mt][1], af[mt][2], af[mt][3],
                             bf[nt][0], bf[nt][1]);
        }
    }
    __syncthreads();

    if (lnw == nullptr) {
        // plain epilogue: bias / resid / relu; fp32 or packed fp16 output
        #pragma unroll
        for (int mt = 0; mt < 4; ++mt) {
            const int r0 = bm + wm * 64 + mt * 16 + g;
            const int r1 = r0 + 8;
            #pragma unroll
            for (int nt = 0; nt < 4; ++nt) {
                const int gc = bn + wn * 32 + nt * 8 + tg * 2;
                float2 o0 = make_float2(acc[mt][nt][0], acc[mt][nt][1]);
                float2 o1 = make_float2(acc[mt][nt][2], acc[mt][nt][3]);
                if (bias) {
                    float2 bb = *(const float2*)&bias[gc];
                    o0.x += bb.x; o0.y += bb.y;
                    o1.x += bb.x; o1.y += bb.y;
                }
                if (r0 < M) {
                    if (resid) {
                        float2 rr = *(const float2*)&resid[(size_t)r0 * NC + gc];
                        o0.x += rr.x; o0.y += rr.y;
                    }
                    if (relu) { o0.x = fmaxf(o0.x, 0.f); o0.y = fmaxf(o0.y, 0.f); }
                    if (Ch) *(half2*)&Ch[(size_t)r0 * NC + gc] = __floats2half2_rn(o0.x, o0.y);
                    else    *(float2*)&C[(size_t)r0 * NC + gc] = o0;
                }
                if (r1 < M) {
                    if (resid) {
                        float2 rr = *(const float2*)&resid[(size_t)r1 * NC + gc];
                        o1.x += rr.x; o1.y += rr.y;
                    }
                    if (relu) { o1.x = fmaxf(o1.x, 0.f); o1.y = fmaxf(o1.y, 0.f); }
                    if (Ch) *(half2*)&Ch[(size_t)r1 * NC + gc] = __floats2half2_rn(o1.x, o1.y);
                    else    *(float2*)&C[(size_t)r1 * NC + gc] = o1;
                }
            }
        }
        return;
    }

    // ---- fused LayerNorm epilogue (NC==128, gridDim.y==1) ----
    #pragma unroll
    for (int mt = 0; mt < 4; ++mt) {
        const int r0 = bm + wm * 64 + mt * 16 + g;
        const int r1 = r0 + 8;
        #pragma unroll
        for (int nt = 0; nt < 4; ++nt) {
            const int gc = wn * 32 + nt * 8 + tg * 2;
            float2 bb = *(const float2*)&bias[gc];
            acc[mt][nt][0] += bb.x; acc[mt][nt][1] += bb.y;
            acc[mt][nt][2] += bb.x; acc[mt][nt][3] += bb.y;
            if (r0 < M) {
                float2 rr = *(const float2*)&resid[(size_t)r0 * NC + gc];
                acc[mt][nt][0] += rr.x; acc[mt][nt][1] += rr.y;
            }
            if (r1 < M) {
                float2 rr = *(const float2*)&resid[(size_t)r1 * NC + gc];
                acc[mt][nt][2] += rr.x; acc[mt][nt][3] += rr.y;
            }
        }
    }
    float* lnsum = smem;            // [128][4]
    float* lnsq  = smem + 512;      // [128][4]
    #pragma unroll
    for (int mt = 0; mt < 4; ++mt) {
        float s0 = 0.f, q0 = 0.f, s1 = 0.f, q1 = 0.f;
        #pragma unroll
        for (int nt = 0; nt < 4; ++nt) {
            float a = acc[mt][nt][0], b = acc[mt][nt][1];
            float c = acc[mt][nt][2], d = acc[mt][nt][3];
            s0 += a + b; q0 += a * a + b * b;
            s1 += c + d; q1 += c * c + d * d;
        }
        #pragma unroll
        for (int o = 1; o < 4; o <<= 1) {
            s0 += __shfl_xor_sync(0xffffffffu, s0, o);
            q0 += __shfl_xor_sync(0xffffffffu, q0, o);
            s1 += __shfl_xor_sync(0xffffffffu, s1, o);
            q1 += __shfl_xor_sync(0xffffffffu, q1, o);
        }
        if (tg == 0) {
            const int lr0 = wm * 64 + mt * 16 + g;
            lnsum[lr0 * 4 + wn] = s0;  lnsq[lr0 * 4 + wn] = q0;
            lnsum[(lr0 + 8) * 4 + wn] = s1;  lnsq[(lr0 + 8) * 4 + wn] = q1;
        }
    }
    __syncthreads();
    #pragma unroll
    for (int mt = 0; mt < 4; ++mt) {
        const int lr0 = wm * 64 + mt * 16 + g;
        const int lr1 = lr0 + 8;
        float4 sv0 = *(const float4*)&lnsum[lr0 * 4];
        float4 qv0 = *(const float4*)&lnsq[lr0 * 4];
        float4 sv1 = *(const float4*)&lnsum[lr1 * 4];
        float4 qv1 = *(const float4*)&lnsq[lr1 * 4];
        float m0 = (sv0.x + sv0.y + sv0.z + sv0.w) * (1.f / 128.f);
        float m1 = (sv1.x + sv1.y + sv1.z + sv1.w) * (1.f / 128.f);
        float v0 = (qv0.x + qv0.y + qv0.z + qv0.w) * (1.f / 128.f) - m0 * m0;
        float v1 = (qv1.x + qv1.y + qv1.z + qv1.w) * (1.f / 128.f) - m1 * m1;
        float rs0 = rsqrtf(v0 + 1e-5f);
        float rs1 = rsqrtf(v1 + 1e-5f);
        const int r0 = bm + lr0;
        const int r1 = bm + lr1;
        #pragma unroll
        for (int nt = 0; nt < 4; ++nt) {
            const int gc = wn * 32 + nt * 8 + tg * 2;
            float2 wv = *(const float2*)&lnw[gc];
            float2 bv = *(const float2*)&lnb[gc];
            if (r0 < M) {
                float2 o;
                o.x = (acc[mt][nt][0] - m0) * rs0 * wv.x + bv.x;
                o.y = (acc[mt][nt][1] - m0) * rs0 * wv.y + bv.y;
                *(float2*)&C[(size_t)r0 * NC + gc] = o;
            }
            if (r1 < M) {
                float2 o;
                o.x = (acc[mt][nt][2] - m1) * rs1 * wv.x + bv.x;
                o.y = (acc[mt][nt][3] - m1) * rs1 * wv.y + bv.y;
                *(float2*)&C[(size_t)r1 * NC + gc] = o;
            }
        }
    }
}

__global__ __launch_bounds__(256, 2) void gemm_tf32(
    const float* __restrict__ A, const float* __restrict__ B,
    const float* __restrict__ bias, const float* __restrict__ resid,
    float* __restrict__ C, int M, int K, int NC, int relu)
{
    gemm_body(A, B, bias, resid, C, nullptr, M, K, NC, relu, nullptr, nullptr);
}

__global__ __launch_bounds__(256, 2) void gemm_tf32_ln(
    const float* __restrict__ A, const float* __restrict__ B,
    const float* __restrict__ bias, const float* __restrict__ resid,
    float* __restrict__ C, int M, int K, int NC,
    const float* __restrict__ lnw, const float* __restrict__ lnb)
{
    gemm_body(A, B, bias, resid, C, nullptr, M, K, NC, 0, lnw, lnb);
}

// fused Q/K/V: blockIdx.z selects weight/bias/output; K and V outputs packed fp16
__global__ __launch_bounds__(256, 2) void gemm_qkv(
    const float* __restrict__ A,
    const float* __restrict__ Bq, const float* __restrict__ Bk, const float* __restrict__ Bv,
    const float* __restrict__ bq, const float* __restrict__ bk, const float* __restrict__ bv,
    float* __restrict__ Cq, __half* __restrict__ Ckh, __half* __restrict__ Cvh,
    int M, int K, int NC)
{
    const int zi = blockIdx.z;
    const float* B  = (zi == 0) ? Bq : (zi == 1) ? Bk : Bv;
    const float* bb = (zi == 0) ? bq : (zi == 1) ? bk : bv;
    float*  C  = (zi == 0) ? Cq : nullptr;
    __half* Ch = (zi == 0) ? nullptr : (zi == 1) ? Ckh : Cvh;
    gemm_body(A, B, bb, nullptr, C, Ch, M, K, NC, 0, nullptr, nullptr);
}

// ---------------- edge attention gather: one warp per dst node, fp16 k/v ----------------
// csr[j] holds the src node id directly (single indirection).
__global__ __launch_bounds__(256) void k_attn(
    const float* __restrict__ q, const __half* __restrict__ kh, const __half* __restrict__ vh,
    const int* __restrict__ off, const int* __restrict__ csr,
    float* __restrict__ attn)
{
    int w = (blockIdx.x * blockDim.x + threadIdx.x) >> 5;
    int lane = threadIdx.x & 31;
    if (w >= N_NODES) return;
    float4 qv = *(const float4*)&q[(size_t)w * DIM + lane * 4];
    float4 acc = make_float4(0.f, 0.f, 0.f, 0.f);
    float z = 0.f;
    int j0 = off[w], j1 = off[w + 1];
    for (int j = j0; j < j1; ++j) {
        int sn = csr[j];
        const size_t base = (size_t)sn * DIM + lane * 4;
        uint2 kr = *(const uint2*)(kh + base);
        uint2 vr = *(const uint2*)(vh + base);
        float2 ka = __half22float2(*(half2*)&kr.x);
        float2 kb = __half22float2(*(half2*)&kr.y);
        float2 va = __half22float2(*(half2*)&vr.x);
        float2 vb = __half22float2(*(half2*)&vr.y);
        float d = ka.x * qv.x + ka.y * qv.y + kb.x * qv.z + kb.y * qv.w;
        d += __shfl_xor_sync(0xffffffffu, d, 1);
        d += __shfl_xor_sync(0xffffffffu, d, 2);
        float sc = __expf(fminf(fmaxf(d * 0.25f, -5.f), 5.f));
        acc.x += va.x * sc; acc.y += va.y * sc; acc.z += vb.x * sc; acc.w += vb.y * sc;
        z += sc;
    }
    float inv = 1.f / (z + 1e-6f);
    float4 o = make_float4(acc.x * inv, acc.y * inv, acc.z * inv, acc.w * inv);
    *(float4*)&attn[(size_t)w * DIM + lane * 4] = o;
}

// ---------------- host ----------------
extern "C" void kernel_launch(void* const* d_in, const int* in_sizes, int n_in,
                              void* d_out, int out_size)
{
    (void)in_sizes; (void)n_in; (void)out_size;
    const float* h_in  = (const float*)d_in[0];
    const int*   src   = (const int*)d_in[1];
    const int*   dst   = (const int*)d_in[2];
    const float* W_emb = (const float*)d_in[3];
    const float* Wq    = (const float*)d_in[4];
    const float* bq    = (const float*)d_in[5];
    const float* Wk    = (const float*)d_in[6];
    const float* bk    = (const float*)d_in[7];
    const float* Wv    = (const float*)d_in[8];
    const float* bv    = (const float*)d_in[9];
    const float* Wo    = (const float*)d_in[10];
    const float* bo    = (const float*)d_in[11];
    const float* ln1w  = (const float*)d_in[12];
    const float* ln1b  = (const float*)d_in[13];
    const float* Wf1   = (const float*)d_in[14];
    const float* bf1   = (const float*)d_in[15];
    const float* Wf2   = (const float*)d_in[16];
    const float* bf2   = (const float*)d_in[17];
    const float* ln2w  = (const float*)d_in[18];
    const float* ln2b  = (const float*)d_in[19];
    float* out = (float*)d_out;

    float *h, *q, *attn, *hx, *f1;
    __half *kh, *vh;
    int *deg, *cur, *off, *csr, *bt, *bo_;
    cudaGetSymbolAddress((void**)&h,    g_h);
    cudaGetSymbolAddress((void**)&q,    g_q);
    cudaGetSymbolAddress((void**)&kh,   g_kh);
    cudaGetSymbolAddress((void**)&vh,   g_vh);
    cudaGetSymbolAddress((void**)&attn, g_attn);
    cudaGetSymbolAddress((void**)&hx,   g_hx);
    cudaGetSymbolAddress((void**)&f1,   g_f1);
    cudaGetSymbolAddress((void**)&deg,  g_deg);
    cudaGetSymbolAddress((void**)&cur,  g_cur);
    cudaGetSymbolAddress((void**)&off,  g_off);
    cudaGetSymbolAddress((void**)&csr,  g_csr);
    cudaGetSymbolAddress((void**)&bt,   g_bt);
    cudaGetSymbolAddress((void**)&bo_,  g_bo);

    // opt-in to >48KB dynamic smem (idempotent; host-side attribute, capture-safe)
    static bool attr_done = false;
    if (!attr_done) {
        cudaFuncSetAttribute(gemm_tf32,    cudaFuncAttributeMaxDynamicSharedMemorySize, SMEM_BYTES);
        cudaFuncSetAttribute(gemm_tf32_ln, cudaFuncAttributeMaxDynamicSharedMemorySize, SMEM_BYTES);
        cudaFuncSetAttribute(gemm_qkv,     cudaFuncAttributeMaxDynamicSharedMemorySize, SMEM_BYTES);
        attr_done = true;
    }

    const int MB = (N_NODES + 127) / 128;                 // 391
    const int WARP_BLOCKS = (N_NODES * 32 + 255) / 256;   // 6250
    const int SCAN_BLOCKS = (N_NODES + 1023) / 1024;      // 49
    const dim3 blk(256);

    // Launch order arranged so ncu (-s 5) lands on a GEMM: slot3=emb, slot5=qkv.
    k_zero2<<<(N_NODES + 256) / 256, blk>>>(deg, N_NODES + 1, cur, N_NODES);      // 0
    k_hist<<<(E_EDGES + 255) / 256, blk>>>(dst, deg, E_EDGES);                    // 1
    k_s1<<<SCAN_BLOCKS, blk>>>(deg, bt);                                          // 2
    gemm_tf32<<<dim3(MB, 1), blk, SMEM_BYTES>>>(h_in, W_emb, nullptr, nullptr,    // 3
                                                h, N_NODES, DIM, DIM, 0);
    k_s2<<<1, 64>>>(bt, bo_, off, SCAN_BLOCKS);                                   // 4

    // layer 0 QKV (depends on emb only)                                          // 5
    gemm_qkv<<<dim3(MB, 1, 3), blk, SMEM_BYTES>>>(h, Wq, Wk, Wv, bq, bk, bv,
                                                  q, kh, vh, N_NODES, DIM, DIM);

    k_s3<<<SCAN_BLOCKS, blk>>>(deg, bo_, off);                                    // 6
    k_fill<<<(E_EDGES + 255) / 256, blk>>>(dst, src, cur, off, csr, E_EDGES);     // 7

    for (int l = 0; l < NLAYERS; ++l) {
        const float* wq = Wq + (size_t)l * DIM * DIM;
        const float* wk = Wk + (size_t)l * DIM * DIM;
        const float* wv = Wv + (size_t)l * DIM * DIM;
        const float* wo = Wo + (size_t)l * DIM * DIM;
        const float* wf1 = Wf1 + (size_t)l * DIM * 2 * DIM;
        const float* wf2 = Wf2 + (size_t)l * 2 * DIM * DIM;

        if (l > 0) {
            gemm_qkv<<<dim3(MB, 1, 3), blk, SMEM_BYTES>>>(h, wq, wk, wv,
                                                          bq + l * DIM, bk + l * DIM, bv + l * DIM,
                                                          q, kh, vh, N_NODES, DIM, DIM);
        }

        k_attn<<<WARP_BLOCKS, blk>>>(q, kh, vh, off, csr, attn);

        // hx = LN1(h + attn @ Wo + bo)   (LN fused into epilogue)
        gemm_tf32_ln<<<dim3(MB, 1), blk, SMEM_BYTES>>>(attn, wo, bo + l * DIM, h, hx,
                                                       N_NODES, DIM, DIM,
                                                       ln1w + l * DIM, ln1b + l * DIM);

        // f1 = relu(hx @ Wf1 + bf1)   [N, 256]
        gemm_tf32<<<dim3(MB, 2), blk, SMEM_BYTES>>>(hx, wf1, bf1 + l * 2 * DIM, nullptr, f1,
                                                    N_NODES, DIM, 2 * DIM, 1);

        // h_next = LN2(hx + f1 @ Wf2 + bf2)   (LN fused)
        float* lnout = (l == NLAYERS - 1) ? out : h;
        gemm_tf32_ln<<<dim3(MB, 1), blk, SMEM_BYTES>>>(f1, wf2, bf2 + l * DIM, hx, lnout,
                                                       N_NODES, 2 * DIM, DIM,
                                                       ln2w + l * DIM, ln2b + l * DIM);
    }
}

// round 15
// speedup vs baseline: 1.6453x; 1.1134x over previous
#include <cuda_runtime.h>
#include <cuda_fp16.h>
#include <math.h>
#include <stdint.h>

#define N_NODES 50000
#define E_EDGES 800000
#define DIM     128
#define NHEADS  8
#define DHEAD   16
#define NLAYERS 2

// fp16 weight buffer offsets (halves)
#define W16_EMB 0
#define W16_Q   16384
#define W16_K   49152
#define W16_V   81920
#define W16_O   114688
#define W16_F1  147456
#define W16_F2  212992
#define W16_TOT 278528

// ---------------- scratch (static device globals; no runtime allocation) ----------------
__device__ float  g_h[N_NODES * DIM];
__device__ float  g_q[N_NODES * DIM];
__device__ float  g_hx[N_NODES * DIM];
__device__ __half g_h16[N_NODES * DIM];
__device__ __half g_hx16[N_NODES * DIM];
__device__ __half g_kh[N_NODES * DIM];
__device__ __half g_vh[N_NODES * DIM];
__device__ __half g_attn16[N_NODES * DIM];
__device__ __half g_f1h[N_NODES * 2 * DIM];
__device__ __half g_hin16[N_NODES * DIM];
__device__ __half g_w16[W16_TOT];
__device__ int    g_deg[N_NODES + 1];
__device__ int    g_cur[N_NODES];
__device__ int    g_off[N_NODES + 1];
__device__ int    g_csr[E_EDGES];     // stores SRC NODE id per CSR slot
__device__ int    g_bt[64];
__device__ int    g_bo[64];

// ---------------- convert fp32 -> fp16 (8 segments in one launch) ----------------
__global__ void k_cvt8(const float* __restrict__ h_in, const float* __restrict__ W_emb,
                       const float* __restrict__ Wq, const float* __restrict__ Wk,
                       const float* __restrict__ Wv, const float* __restrict__ Wo,
                       const float* __restrict__ Wf1, const float* __restrict__ Wf2,
                       __half* __restrict__ hin16, __half* __restrict__ w16) {
    const float* src; __half* dst; int n;
    switch (blockIdx.y) {
        case 0: src = h_in;  dst = hin16;          n = N_NODES * DIM; break;
        case 1: src = W_emb; dst = w16 + W16_EMB;  n = 16384; break;
        case 2: src = Wq;    dst = w16 + W16_Q;    n = 32768; break;
        case 3: src = Wk;    dst = w16 + W16_K;    n = 32768; break;
        case 4: src = Wv;    dst = w16 + W16_V;    n = 32768; break;
        case 5: src = Wo;    dst = w16 + W16_O;    n = 32768; break;
        case 6: src = Wf1;   dst = w16 + W16_F1;   n = 65536; break;
        default: src = Wf2;  dst = w16 + W16_F2;   n = 65536; break;
    }
    int i = blockIdx.x * blockDim.x + threadIdx.x;
    if (i < (n >> 2)) {
        float4 v = ((const float4*)src)[i];
        half2 p0 = __floats2half2_rn(v.x, v.y);
        half2 p1 = __floats2half2_rn(v.z, v.w);
        ((half2*)dst)[i * 2]     = p0;
        ((half2*)dst)[i * 2 + 1] = p1;
    }
}

// ---------------- small utility kernels ----------------
__global__ void k_zero2(int* a, int na, int* b, int nb) {
    int i = blockIdx.x * blockDim.x + threadIdx.x;
    if (i < na) a[i] = 0;
    if (i < nb) b[i] = 0;
}

__global__ void k_hist(const int* __restrict__ dst, int* __restrict__ deg, int e) {
    int i = blockIdx.x * blockDim.x + threadIdx.x;
    if (i < e) atomicAdd(&deg[dst[i]], 1);
}

__global__ void k_s1(const int* __restrict__ deg, int* __restrict__ bt) {
    int b = blockIdx.x, t = threadIdx.x, lane = t & 31, w = t >> 5;
    int base = b * 1024 + t * 4;
    int s = 0;
    #pragma unroll
    for (int j = 0; j < 4; ++j) { int i = base + j; if (i < N_NODES) s += deg[i]; }
    #pragma unroll
    for (int o = 16; o > 0; o >>= 1) s += __shfl_xor_sync(0xffffffffu, s, o);
    __shared__ int ws[8];
    if (lane == 0) ws[w] = s;
    __syncthreads();
    if (t == 0) {
        int tt = 0;
        #pragma unroll
        for (int i = 0; i < 8; ++i) tt += ws[i];
        bt[b] = tt;
    }
}

__global__ void k_s2(const int* __restrict__ bt, int* __restrict__ bo,
                     int* __restrict__ off, int nb) {
    __shared__ int sm[64];
    int t = threadIdx.x;
    int v = (t < nb) ? bt[t] : 0;
    sm[t] = v;
    __syncthreads();
    for (int o = 1; o < 64; o <<= 1) {
        int u = (t >= o) ? sm[t - o] : 0;
        __syncthreads();
        sm[t] += u;
        __syncthreads();
    }
    if (t < nb) bo[t] = sm[t] - v;
    if (t == 0) off[N_NODES] = E_EDGES;
}

__global__ void k_s3(const int* __restrict__ deg, const int* __restrict__ bo,
                     int* __restrict__ off) {
    int b = blockIdx.x, t = threadIdx.x, lane = t & 31, w = t >> 5;
    int base = b * 1024 + t * 4;
    int d[4];
    #pragma unroll
    for (int j = 0; j < 4; ++j) { int i = base + j; d[j] = (i < N_NODES) ? deg[i] : 0; }
    int tsum = d[0] + d[1] + d[2] + d[3];
    int inc = tsum;
    #pragma unroll
    for (int o = 1; o < 32; o <<= 1) {
        int u = __shfl_up_sync(0xffffffffu, inc, o);
        if (lane >= o) inc += u;
    }
    int exc = inc - tsum;
    __shared__ int ws[8];
    if (lane == 31) ws[w] = inc;
    __syncthreads();
    int woff = 0;
    for (int i = 0; i < w; ++i) woff += ws[i];
    int run = bo[b] + woff + exc;
    #pragma unroll
    for (int j = 0; j < 4; ++j) {
        int i = base + j;
        if (i < N_NODES) off[i] = run;
        run += d[j];
    }
}

__global__ void k_fill(const int* __restrict__ dst, const int* __restrict__ src,
                       int* __restrict__ cur, const int* __restrict__ off,
                       int* __restrict__ csr, int e) {
    int i = blockIdx.x * blockDim.x + threadIdx.x;
    if (i < e) {
        int d = dst[i];
        int p = atomicAdd(&cur[d], 1);
        csr[off[d] + p] = src[i];
    }
}

// ---------------- FP16 tensor-core GEMM (m16n8k16), BK=16, 4-stage cp.async ----------------
// C[M,NC] = A16[M,K] @ B16[K,NC] (+bias fp32)(+resid fp32)(relu?)(+fused LN)
// Outputs: C32 (fp32) and/or C16 (fp16) — either may be null (except LN needs C32).
// BM=128 BN=128 BK=16, 256 threads, warps 2(m) x 4(n), warp tile 64x32.
// A staged [m][16+8pad] halves; B staged [k][128+8pad] halves; ldmatrix fragments.

#define A16_STG (128 * 24)   // halves per stage
#define B16_STG (16 * 136)   // halves per stage
#define NSTG  4
#define SMEM_BYTES ((NSTG * (A16_STG + B16_STG)) * 2)

__device__ __forceinline__ void cp16(uint32_t saddr, const void* gaddr, bool pred) {
    int sz = pred ? 16 : 0;
    asm volatile("cp.async.cg.shared.global [%0], [%1], 16, %2;\n"
                 :: "r"(saddr), "l"(gaddr), "r"(sz));
}
__device__ __forceinline__ void cp_commit() { asm volatile("cp.async.commit_group;\n"); }
__device__ __forceinline__ void cp_wait2() { asm volatile("cp.async.wait_group 2;\n"); }
__device__ __forceinline__ void cp_wait1() { asm volatile("cp.async.wait_group 1;\n"); }
__device__ __forceinline__ void cp_wait0() { asm volatile("cp.async.wait_group 0;\n"); }

__device__ __forceinline__ void ldsm4(uint32_t& r0, uint32_t& r1, uint32_t& r2,
                                      uint32_t& r3, uint32_t addr) {
    asm volatile("ldmatrix.sync.aligned.m8n8.x4.shared.b16 {%0,%1,%2,%3}, [%4];"
                 : "=r"(r0), "=r"(r1), "=r"(r2), "=r"(r3) : "r"(addr));
}
__device__ __forceinline__ void ldsm4t(uint32_t& r0, uint32_t& r1, uint32_t& r2,
                                       uint32_t& r3, uint32_t addr) {
    asm volatile("ldmatrix.sync.aligned.m8n8.x4.trans.shared.b16 {%0,%1,%2,%3}, [%4];"
                 : "=r"(r0), "=r"(r1), "=r"(r2), "=r"(r3) : "r"(addr));
}
__device__ __forceinline__ void mma_f16(float c[4], uint32_t a0, uint32_t a1,
                                        uint32_t a2, uint32_t a3,
                                        uint32_t b0, uint32_t b1) {
    asm volatile(
        "mma.sync.aligned.m16n8k16.row.col.f32.f16.f16.f32 "
        "{%0,%1,%2,%3}, {%4,%5,%6,%7}, {%8,%9}, {%0,%1,%2,%3};\n"
        : "+f"(c[0]), "+f"(c[1]), "+f"(c[2]), "+f"(c[3])
        : "r"(a0), "r"(a1), "r"(a2), "r"(a3), "r"(b0), "r"(b1));
}

__device__ __forceinline__ void gemm16_body(
    const __half* __restrict__ A, const __half* __restrict__ B,
    const float* __restrict__ bias, const float* __restrict__ resid,
    float* __restrict__ C, __half* __restrict__ Ch,
    int M, int K, int NC, int relu,
    const float* __restrict__ lnw, const float* __restrict__ lnb)
{
    extern __shared__ __half smem16[];
    __half* Asm = smem16;                       // [NSTG][128][24]
    __half* Bsm = smem16 + NSTG * A16_STG;      // [NSTG][16][136]

    const int tid = threadIdx.x;
    const int lane = tid & 31;
    const int wid = tid >> 5;
    const int wm = wid >> 2;       // 0..1
    const int wn = wid & 3;        // 0..3
    const int g  = lane >> 2;      // 0..7
    const int tg = lane & 3;       // 0..3

    const int bm = blockIdx.x * 128;
    const int bn = blockIdx.y * 128;

    // loaders: A -> row tid>>1, 8-half chunk (tid&1); B -> row tid>>4, chunk (tid&15)
    const int a_r = tid >> 1;
    const int a_c = (tid & 1) * 8;
    const int b_r = tid >> 4;
    const int b_c = (tid & 15) * 8;
    const bool av = (bm + a_r) < M;

    const uint32_t sA = (uint32_t)__cvta_generic_to_shared(Asm);
    const uint32_t sB = (uint32_t)__cvta_generic_to_shared(Bsm);
    const uint32_t sa = sA + (uint32_t)(a_r * 24 + a_c) * 2;
    const uint32_t sb = sB + (uint32_t)(b_r * 136 + b_c) * 2;
    const __half* ga = A + (size_t)(bm + a_r) * K + a_c;
    const __half* gb = B + (size_t)b_r * NC + bn + b_c;

    float acc[4][4][4];
    #pragma unroll
    for (int i = 0; i < 4; ++i)
        #pragma unroll
        for (int j = 0; j < 4; ++j)
            #pragma unroll
            for (int r = 0; r < 4; ++r) acc[i][j][r] = 0.f;

    const int iters = K >> 4;

    // ldmatrix lane address components
    const int a_row_l = (lane & 15);            // m within 16-row tile
    const int a_koff  = (lane >> 4) * 8;        // 0 or 8
    const int b_krow  = (lane & 15);            // k row
    const int b_noff  = ((lane >> 4) & 1) * 8;  // 0 or 8 within 16-col pair

    // prologue: stages 0..NSTG-2
    #pragma unroll
    for (int st = 0; st < NSTG - 1; ++st) {
        const int k0 = st * 16;
        cp16(sa + (uint32_t)(st * A16_STG) * 2, ga + k0, av);
        cp16(sb + (uint32_t)(st * B16_STG) * 2, gb + (size_t)k0 * NC, true);
        cp_commit();
    }

    for (int kt = 0; kt < iters; ++kt) {
        const int st = kt % NSTG;
        if (kt <= iters - 3)      cp_wait2();
        else if (kt == iters - 2) cp_wait1();
        else                      cp_wait0();
        __syncthreads();

        if (kt + NSTG - 1 < iters) {
            const int ns = (kt + NSTG - 1) % NSTG;
            const int k0 = (kt + NSTG - 1) * 16;
            cp16(sa + (uint32_t)(ns * A16_STG) * 2, ga + k0, av);
            cp16(sb + (uint32_t)(ns * B16_STG) * 2, gb + (size_t)k0 * NC, true);
            cp_commit();
        }

        const uint32_t aBase = sA + (uint32_t)(st * A16_STG) * 2;
        const uint32_t bBase = sB + (uint32_t)(st * B16_STG) * 2;

        uint32_t af[4][4], bf[4][2];
        #pragma unroll
        for (int mt = 0; mt < 4; ++mt) {
            const int row = wm * 64 + mt * 16 + a_row_l;
            ldsm4(af[mt][0], af[mt][1], af[mt][2], af[mt][3],
                  aBase + (uint32_t)(row * 24 + a_koff) * 2);
        }
        #pragma unroll
        for (int ntp = 0; ntp < 2; ++ntp) {
            const int col = wn * 32 + ntp * 16 + b_noff;
            uint32_t r0, r1, r2, r3;
            ldsm4t(r0, r1, r2, r3, bBase + (uint32_t)(b_krow * 136 + col) * 2);
            bf[ntp * 2][0] = r0;  bf[ntp * 2][1] = r1;
            bf[ntp * 2 + 1][0] = r2;  bf[ntp * 2 + 1][1] = r3;
        }
        #pragma unroll
        for (int mt = 0; mt < 4; ++mt)
            #pragma unroll
            for (int nt = 0; nt < 4; ++nt)
                mma_f16(acc[mt][nt], af[mt][0], af[mt][1], af[mt][2], af[mt][3],
                        bf[nt][0], bf[nt][1]);
    }
    __syncthreads();

    if (lnw == nullptr) {
        // plain epilogue: bias / resid / relu; fp32 and/or fp16 stores
        #pragma unroll
        for (int mt = 0; mt < 4; ++mt) {
            const int r0 = bm + wm * 64 + mt * 16 + g;
            const int r1 = r0 + 8;
            #pragma unroll
            for (int nt = 0; nt < 4; ++nt) {
                const int gc = bn + wn * 32 + nt * 8 + tg * 2;
                float2 o0 = make_float2(acc[mt][nt][0], acc[mt][nt][1]);
                float2 o1 = make_float2(acc[mt][nt][2], acc[mt][nt][3]);
                if (bias) {
                    float2 bb = *(const float2*)&bias[gc];
                    o0.x += bb.x; o0.y += bb.y;
                    o1.x += bb.x; o1.y += bb.y;
                }
                if (r0 < M) {
                    if (resid) {
                        float2 rr = *(const float2*)&resid[(size_t)r0 * NC + gc];
                        o0.x += rr.x; o0.y += rr.y;
                    }
                    if (relu) { o0.x = fmaxf(o0.x, 0.f); o0.y = fmaxf(o0.y, 0.f); }
                    if (C)  *(float2*)&C[(size_t)r0 * NC + gc] = o0;
                    if (Ch) *(half2*)&Ch[(size_t)r0 * NC + gc] = __floats2half2_rn(o0.x, o0.y);
                }
                if (r1 < M) {
                    if (resid) {
                        float2 rr = *(const float2*)&resid[(size_t)r1 * NC + gc];
                        o1.x += rr.x; o1.y += rr.y;
                    }
                    if (relu) { o1.x = fmaxf(o1.x, 0.f); o1.y = fmaxf(o1.y, 0.f); }
                    if (C)  *(float2*)&C[(size_t)r1 * NC + gc] = o1;
                    if (Ch) *(half2*)&Ch[(size_t)r1 * NC + gc] = __floats2half2_rn(o1.x, o1.y);
                }
            }
        }
        return;
    }

    // ---- fused LayerNorm epilogue (NC==128, gridDim.y==1) ----
    #pragma unroll
    for (int mt = 0; mt < 4; ++mt) {
        const int r0 = bm + wm * 64 + mt * 16 + g;
        const int r1 = r0 + 8;
        #pragma unroll
        for (int nt = 0; nt < 4; ++nt) {
            const int gc = wn * 32 + nt * 8 + tg * 2;
            float2 bb = *(const float2*)&bias[gc];
            acc[mt][nt][0] += bb.x; acc[mt][nt][1] += bb.y;
            acc[mt][nt][2] += bb.x; acc[mt][nt][3] += bb.y;
            if (r0 < M) {
                float2 rr = *(const float2*)&resid[(size_t)r0 * NC + gc];
                acc[mt][nt][0] += rr.x; acc[mt][nt][1] += rr.y;
            }
            if (r1 < M) {
                float2 rr = *(const float2*)&resid[(size_t)r1 * NC + gc];
                acc[mt][nt][2] += rr.x; acc[mt][nt][3] += rr.y;
            }
        }
    }
    float* lnsum = (float*)smem16;            // [128][4]
    float* lnsq  = ((float*)smem16) + 512;    // [128][4]
    #pragma unroll
    for (int mt = 0; mt < 4; ++mt) {
        float s0 = 0.f, q0 = 0.f, s1 = 0.f, q1 = 0.f;
        #pragma unroll
        for (int nt = 0; nt < 4; ++nt) {
            float a = acc[mt][nt][0], b = acc[mt][nt][1];
            float c = acc[mt][nt][2], d = acc[mt][nt][3];
            s0 += a + b; q0 += a * a + b * b;
            s1 += c + d; q1 += c * c + d * d;
        }
        #pragma unroll
        for (int o = 1; o < 4; o <<= 1) {
            s0 += __shfl_xor_sync(0xffffffffu, s0, o);
            q0 += __shfl_xor_sync(0xffffffffu, q0, o);
            s1 += __shfl_xor_sync(0xffffffffu, s1, o);
            q1 += __shfl_xor_sync(0xffffffffu, q1, o);
        }
        if (tg == 0) {
            const int lr0 = wm * 64 + mt * 16 + g;
            lnsum[lr0 * 4 + wn] = s0;  lnsq[lr0 * 4 + wn] = q0;
            lnsum[(lr0 + 8) * 4 + wn] = s1;  lnsq[(lr0 + 8) * 4 + wn] = q1;
        }
    }
    __syncthreads();
    #pragma unroll
    for (int mt = 0; mt < 4; ++mt) {
        const int lr0 = wm * 64 + mt * 16 + g;
        const int lr1 = lr0 + 8;
        float4 sv0 = *(const float4*)&lnsum[lr0 * 4];
        float4 qv0 = *(const float4*)&lnsq[lr0 * 4];
        float4 sv1 = *(const float4*)&lnsum[lr1 * 4];
        float4 qv1 = *(const float4*)&lnsq[lr1 * 4];
        float m0 = (sv0.x + sv0.y + sv0.z + sv0.w) * (1.f / 128.f);
        float m1 = (sv1.x + sv1.y + sv1.z + sv1.w) * (1.f / 128.f);
        float v0 = (qv0.x + qv0.y + qv0.z + qv0.w) * (1.f / 128.f) - m0 * m0;
        float v1 = (qv1.x + qv1.y + qv1.z + qv1.w) * (1.f / 128.f) - m1 * m1;
        float rs0 = rsqrtf(v0 + 1e-5f);
        float rs1 = rsqrtf(v1 + 1e-5f);
        const int r0 = bm + lr0;
        const int r1 = bm + lr1;
        #pragma unroll
        for (int nt = 0; nt < 4; ++nt) {
            const int gc = wn * 32 + nt * 8 + tg * 2;
            float2 wv = *(const float2*)&lnw[gc];
            float2 bv = *(const float2*)&lnb[gc];
            if (r0 < M) {
                float2 o;
                o.x = (acc[mt][nt][0] - m0) * rs0 * wv.x + bv.x;
                o.y = (acc[mt][nt][1] - m0) * rs0 * wv.y + bv.y;
                *(float2*)&C[(size_t)r0 * NC + gc] = o;
                if (Ch) *(half2*)&Ch[(size_t)r0 * NC + gc] = __floats2half2_rn(o.x, o.y);
            }
            if (r1 < M) {
                float2 o;
                o.x = (acc[mt][nt][2] - m1) * rs1 * wv.x + bv.x;
                o.y = (acc[mt][nt][3] - m1) * rs1 * wv.y + bv.y;
                *(float2*)&C[(size_t)r1 * NC + gc] = o;
                if (Ch) *(half2*)&Ch[(size_t)r1 * NC + gc] = __floats2half2_rn(o.x, o.y);
            }
        }
    }
}

__global__ __launch_bounds__(256, 2) void gemm16(
    const __half* __restrict__ A, const __half* __restrict__ B,
    const float* __restrict__ bias, const float* __restrict__ resid,
    float* __restrict__ C, __half* __restrict__ Ch,
    int M, int K, int NC, int relu)
{
    gemm16_body(A, B, bias, resid, C, Ch, M, K, NC, relu, nullptr, nullptr);
}

__global__ __launch_bounds__(256, 2) void gemm16_ln(
    const __half* __restrict__ A, const __half* __restrict__ B,
    const float* __restrict__ bias, const float* __restrict__ resid,
    float* __restrict__ C, __half* __restrict__ Ch,
    int M, int K, int NC,
    const float* __restrict__ lnw, const float* __restrict__ lnb)
{
    gemm16_body(A, B, bias, resid, C, Ch, M, K, NC, 0, lnw, lnb);
}

// fused Q/K/V: blockIdx.z selects weight/bias/output; q fp32, k/v fp16
__global__ __launch_bounds__(256, 2) void gemm16_qkv(
    const __half* __restrict__ A,
    const __half* __restrict__ Bq, const __half* __restrict__ Bk, const __half* __restrict__ Bv,
    const float* __restrict__ bq, const float* __restrict__ bk, const float* __restrict__ bv,
    float* __restrict__ Cq, __half* __restrict__ Ckh, __half* __restrict__ Cvh,
    int M, int K, int NC)
{
    const int zi = blockIdx.z;
    const __half* B  = (zi == 0) ? Bq : (zi == 1) ? Bk : Bv;
    const float*  bb = (zi == 0) ? bq : (zi == 1) ? bk : bv;
    float*  C  = (zi == 0) ? Cq : nullptr;
    __half* Ch = (zi == 0) ? nullptr : (zi == 1) ? Ckh : Cvh;
    gemm16_body(A, B, bb, nullptr, C, Ch, M, K, NC, 0, nullptr, nullptr);
}

// ---------------- edge attention gather: one warp per dst node, fp16 k/v, fp16 out ----------------
__global__ __launch_bounds__(256) void k_attn(
    const float* __restrict__ q, const __half* __restrict__ kh, const __half* __restrict__ vh,
    const int* __restrict__ off, const int* __restrict__ csr,
    __half* __restrict__ attn16)
{
    int w = (blockIdx.x * blockDim.x + threadIdx.x) >> 5;
    int lane = threadIdx.x & 31;
    if (w >= N_NODES) return;
    float4 qv = *(const float4*)&q[(size_t)w * DIM + lane * 4];
    float4 acc = make_float4(0.f, 0.f, 0.f, 0.f);
    float z = 0.f;
    int j0 = off[w], j1 = off[w + 1];
    for (int j = j0; j < j1; ++j) {
        int sn = csr[j];
        const size_t base = (size_t)sn * DIM + lane * 4;
        uint2 kr = *(const uint2*)(kh + base);
        uint2 vr = *(const uint2*)(vh + base);
        float2 ka = __half22float2(*(half2*)&kr.x);
        float2 kb = __half22float2(*(half2*)&kr.y);
        float2 va = __half22float2(*(half2*)&vr.x);
        float2 vb = __half22float2(*(half2*)&vr.y);
        float d = ka.x * qv.x + ka.y * qv.y + kb.x * qv.z + kb.y * qv.w;
        d += __shfl_xor_sync(0xffffffffu, d, 1);
        d += __shfl_xor_sync(0xffffffffu, d, 2);
        float sc = __expf(fminf(fmaxf(d * 0.25f, -5.f), 5.f));
        acc.x += va.x * sc; acc.y += va.y * sc; acc.z += vb.x * sc; acc.w += vb.y * sc;
        z += sc;
    }
    float inv = 1.f / (z + 1e-6f);
    half2 p0 = __floats2half2_rn(acc.x * inv, acc.y * inv);
    half2 p1 = __floats2half2_rn(acc.z * inv, acc.w * inv);
    uint2 o;
    o.x = *(uint32_t*)&p0;
    o.y = *(uint32_t*)&p1;
    *(uint2*)&attn16[(size_t)w * DIM + lane * 4] = o;
}

// ---------------- host ----------------
extern "C" void kernel_launch(void* const* d_in, const int* in_sizes, int n_in,
                              void* d_out, int out_size)
{
    (void)in_sizes; (void)n_in; (void)out_size;
    const float* h_in  = (const float*)d_in[0];
    const int*   src   = (const int*)d_in[1];
    const int*   dst   = (const int*)d_in[2];
    const float* W_emb = (const float*)d_in[3];
    const float* Wq    = (const float*)d_in[4];
    const float* bq    = (const float*)d_in[5];
    const float* Wk    = (const float*)d_in[6];
    const float* bk    = (const float*)d_in[7];
    const float* Wv    = (const float*)d_in[8];
    const float* bv    = (const float*)d_in[9];
    const float* Wo    = (const float*)d_in[10];
    const float* bo    = (const float*)d_in[11];
    const float* ln1w  = (const float*)d_in[12];
    const float* ln1b  = (const float*)d_in[13];
    const float* Wf1   = (const float*)d_in[14];
    const float* bf1   = (const float*)d_in[15];
    const float* Wf2   = (const float*)d_in[16];
    const float* bf2   = (const float*)d_in[17];
    const float* ln2w  = (const float*)d_in[18];
    const float* ln2b  = (const float*)d_in[19];
    float* out = (float*)d_out;

    float *h, *q, *hx;
    __half *h16, *hx16, *kh, *vh, *attn16, *f1h, *hin16, *w16;
    int *deg, *cur, *off, *csr, *bt, *bo_;
    cudaGetSymbolAddress((void**)&h,      g_h);
    cudaGetSymbolAddress((void**)&q,      g_q);
    cudaGetSymbolAddress((void**)&hx,     g_hx);
    cudaGetSymbolAddress((void**)&h16,    g_h16);
    cudaGetSymbolAddress((void**)&hx16,   g_hx16);
    cudaGetSymbolAddress((void**)&kh,     g_kh);
    cudaGetSymbolAddress((void**)&vh,     g_vh);
    cudaGetSymbolAddress((void**)&attn16, g_attn16);
    cudaGetSymbolAddress((void**)&f1h,    g_f1h);
    cudaGetSymbolAddress((void**)&hin16,  g_hin16);
    cudaGetSymbolAddress((void**)&w16,    g_w16);
    cudaGetSymbolAddress((void**)&deg,    g_deg);
    cudaGetSymbolAddress((void**)&cur,    g_cur);
    cudaGetSymbolAddress((void**)&off,    g_off);
    cudaGetSymbolAddress((void**)&csr,    g_csr);
    cudaGetSymbolAddress((void**)&bt,     g_bt);
    cudaGetSymbolAddress((void**)&bo_,    g_bo);

    static bool attr_done = false;
    if (!attr_done) {
        cudaFuncSetAttribute(gemm16,     cudaFuncAttributeMaxDynamicSharedMemorySize, SMEM_BYTES);
        cudaFuncSetAttribute(gemm16_ln,  cudaFuncAttributeMaxDynamicSharedMemorySize, SMEM_BYTES);
        cudaFuncSetAttribute(gemm16_qkv, cudaFuncAttributeMaxDynamicSharedMemorySize, SMEM_BYTES);
        attr_done = true;
    }

    const int MB = (N_NODES + 127) / 128;                 // 391
    const int WARP_BLOCKS = (N_NODES * 32 + 255) / 256;   // 6250
    const int SCAN_BLOCKS = (N_NODES + 1023) / 1024;      // 49
    const int CVT_BLOCKS  = (N_NODES * DIM / 4 + 255) / 256;  // 6250
    const dim3 blk(256);

    // fp32->fp16 conversions (input + all weights) in one launch
    k_cvt8<<<dim3(CVT_BLOCKS, 8), blk>>>(h_in, W_emb, Wq, Wk, Wv, Wo, Wf1, Wf2,
                                         hin16, w16);

    // CSR build
    k_zero2<<<(N_NODES + 256) / 256, blk>>>(deg, N_NODES + 1, cur, N_NODES);
    k_hist<<<(E_EDGES + 255) / 256, blk>>>(dst, deg, E_EDGES);
    k_s1<<<SCAN_BLOCKS, blk>>>(deg, bt);
    k_s2<<<1, 64>>>(bt, bo_, off, SCAN_BLOCKS);
    k_s3<<<SCAN_BLOCKS, blk>>>(deg, bo_, off);
    k_fill<<<(E_EDGES + 255) / 256, blk>>>(dst, src, cur, off, csr, E_EDGES);

    // embedding: h = h_in @ W_emb  (fp32 + fp16 outputs)
    gemm16<<<dim3(MB, 1), blk, SMEM_BYTES>>>(hin16, w16 + W16_EMB, nullptr, nullptr,
                                             h, h16, N_NODES, DIM, DIM, 0);

    for (int l = 0; l < NLAYERS; ++l) {
        const __half* wq16  = w16 + W16_Q  + (size_t)l * DIM * DIM;
        const __half* wk16  = w16 + W16_K  + (size_t)l * DIM * DIM;
        const __half* wv16  = w16 + W16_V  + (size_t)l * DIM * DIM;
        const __half* wo16  = w16 + W16_O  + (size_t)l * DIM * DIM;
        const __half* wf116 = w16 + W16_F1 + (size_t)l * DIM * 2 * DIM;
        const __half* wf216 = w16 + W16_F2 + (size_t)l * 2 * DIM * DIM;

        gemm16_qkv<<<dim3(MB, 1, 3), blk, SMEM_BYTES>>>(h16, wq16, wk16, wv16,
                                                        bq + l * DIM, bk + l * DIM, bv + l * DIM,
                                                        q, kh, vh, N_NODES, DIM, DIM);

        k_attn<<<WARP_BLOCKS, blk>>>(q, kh, vh, off, csr, attn16);

        // hx = LN1(h + attn @ Wo + bo)  -> fp32 hx + fp16 hx16
        gemm16_ln<<<dim3(MB, 1), blk, SMEM_BYTES>>>(attn16, wo16, bo + l * DIM, h,
                                                    hx, hx16, N_NODES, DIM, DIM,
                                                    ln1w + l * DIM, ln1b + l * DIM);

        // f1 = relu(hx @ Wf1 + bf1)  [N, 256] fp16 only
        gemm16<<<dim3(MB, 2), blk, SMEM_BYTES>>>(hx16, wf116, bf1 + l * 2 * DIM, nullptr,
                                                 nullptr, f1h, N_NODES, DIM, 2 * DIM, 1);

        // h_next = LN2(hx + f1 @ Wf2 + bf2)  -> fp32 (h or out) + fp16 h16 (if more layers)
        float*  lnout  = (l == NLAYERS - 1) ? out : h;
        __half* lnout16 = (l == NLAYERS - 1) ? nullptr : h16;
        gemm16_ln<<<dim3(MB, 1), blk, SMEM_BYTES>>>(f1h, wf216, bf2 + l * DIM, hx,
                                                    lnout, lnout16, N_NODES, 2 * DIM, DIM,
                                                    ln2w + l * DIM, ln2b + l * DIM);
    }
}